// round 14
// baseline (speedup 1.0000x reference)
#include <cuda_runtime.h>

// Problem constants (fixed shapes from reference)
#define BATCH 8
#define TLEN  4096
#define BC    256
#define RC    64
#define NB0   4
#define NB1   3
#define TB    7           // NB0 + NB1
#define CH0   1024        // x0 channels
#define CH1   768         // x1 channels

// Device-global scratch (allocation-free per harness rules)
__device__ float g_gap[BATCH * BC];
__device__ float g_scores[TB * BATCH * BC];   // [k][b][c], raw scores

// 32-byte evict_last load (sm_103 ptxas requires v8.b32/v4.b64 for this hint).
// ALL gap loads use this: L2 keeps the ~120MB LRU tail of x in the evict_last
// class; scale's evict-first loads/stores cannot displace it, so the tail is
// re-read from L2 in the scale pass.
__device__ __forceinline__ float ld_evict_last32_sum(const float* p) {
    unsigned long long r0, r1, r2, r3;
    asm volatile("ld.global.nc.L2::evict_last.v4.b64 {%0,%1,%2,%3}, [%4];"
                 : "=l"(r0), "=l"(r1), "=l"(r2), "=l"(r3) : "l"(p));
    float2 a = *reinterpret_cast<float2*>(&r0);
    float2 b = *reinterpret_cast<float2*>(&r1);
    float2 c = *reinterpret_cast<float2*>(&r2);
    float2 d = *reinterpret_cast<float2*>(&r3);
    return ((a.x + a.y) + (b.x + b.y)) + ((c.x + c.y) + (d.x + d.y));
}

// ---------------------------------------------------------------------------
// Kernel 1: block-sum over channel blocks + GAP over time.
// grid = 2048 blocks, 256 threads, min 8 CTAs/SM. Single code path: all
// loads are 32B evict_last. Triggers PDL completion after publishing g_gap.
// ---------------------------------------------------------------------------
__global__ void __launch_bounds__(256, 8) gap_kernel(const float* __restrict__ x0,
                                                     const float* __restrict__ x1) {
    const int b = blockIdx.x >> 8;      // / BC
    const int c = blockIdx.x & (BC - 1);
    const int tid = threadIdx.x;

    float acc = 0.0f;

    #pragma unroll
    for (int blk = 0; blk < NB0; ++blk) {
        const float* row = x0 + ((size_t)b * CH0 + (size_t)blk * BC + c) * TLEN;
        #pragma unroll
        for (int i = 0; i < 2; ++i)
            acc += ld_evict_last32_sum(row + (tid + i * 256) * 8);
    }
    #pragma unroll
    for (int blk = 0; blk < NB1; ++blk) {
        const float* row = x1 + ((size_t)b * CH1 + (size_t)blk * BC + c) * TLEN;
        #pragma unroll
        for (int i = 0; i < 2; ++i)
            acc += ld_evict_last32_sum(row + (tid + i * 256) * 8);
    }

    // Block reduction
    __shared__ float warpsum[8];
    #pragma unroll
    for (int o = 16; o > 0; o >>= 1)
        acc += __shfl_down_sync(0xffffffffu, acc, o);
    if ((tid & 31) == 0) warpsum[tid >> 5] = acc;
    __syncthreads();
    if (tid < 8) {
        float v = warpsum[tid];
        #pragma unroll
        for (int o = 4; o > 0; o >>= 1)
            v += __shfl_down_sync(0x000000ffu, v, o);
        if (tid == 0) g_gap[b * BC + c] = v * (1.0f / (float)TLEN);
    }
    __syncthreads();
    cudaTriggerProgrammaticLaunchCompletion();
}

// ---------------------------------------------------------------------------
// Kernel 2: fused h + raw scores. grid = TB*BATCH (56) blocks x 256 threads.
// PDL-dependent on gap_kernel.
// ---------------------------------------------------------------------------
__global__ void __launch_bounds__(256) score_kernel(const float* __restrict__ W1,
                                                    const float* __restrict__ b1,
                                                    const float* __restrict__ gamma,
                                                    const float* __restrict__ beta,
                                                    const float* __restrict__ Wh,
                                                    const float* __restrict__ bh) {
    const int k = blockIdx.x >> 3;       // / BATCH
    const int b = blockIdx.x & 7;
    const int tid = threadIdx.x;

    __shared__ float part[4][RC];        // split-K partials
    __shared__ float h_s[RC];

    cudaGridDependencySynchronize();     // wait for gap's g_gap writes

    // --- h[b] split-K: thread (s, r) accumulates over c in [s*64, s*64+64)
    {
        const int s = tid >> 6;          // 0..3
        const int r = tid & (RC - 1);    // 0..63
        const float* gp = &g_gap[b * BC + s * 64];
        const float* wp = W1 + (size_t)(s * 64) * RC + r;
        float acc = 0.0f;
        #pragma unroll 16
        for (int i = 0; i < 64; ++i)
            acc = fmaf(gp[i], wp[(size_t)i * RC], acc);   // coalesced: r varies
        part[s][r] = acc;
    }
    __syncthreads();
    if (tid < RC) {
        const int r = tid;
        float s = part[0][r] + part[1][r] + part[2][r] + part[3][r] + b1[r];
        const float bnscale = gamma[r] * rsqrtf(1.0f + 1e-5f);
        h_s[r] = fmaxf(fmaf(s, bnscale, beta[r]), 0.0f);
    }
    __syncthreads();

    // --- score[k][b][c], c = tid; Wh reads coalesced across c ---
    const int c = tid;
    float s = bh[k * BC + c];
    const float* w = Wh + (size_t)k * RC * BC + c;
    #pragma unroll 16
    for (int r = 0; r < RC; ++r)
        s = fmaf(h_s[r], w[(size_t)r * BC], s);
    g_scores[(k * BATCH + b) * BC + c] = s;

    cudaTriggerProgrammaticLaunchCompletion();
}

// ---------------------------------------------------------------------------
// Kernel 3: streaming scale with block-level fused softmax. PDL-dependent on
// score_kernel: each CTA issues its 4 independent x loads FIRST, then waits
// on the dependency, so the wait hides under the load latency.
// ---------------------------------------------------------------------------
__global__ void __launch_bounds__(256, 8) scale_kernel(const float* __restrict__ x0,
                                                       const float* __restrict__ x1,
                                                       float* __restrict__ out) {
    const int bid = blockIdx.x;
    const int tid = threadIdx.x;

    const float* src;
    float* dst;
    int b, ch, kblk;
    if (bid < BATCH * CH0) {
        b = bid >> 10;            // / CH0
        ch = bid & (CH0 - 1);
        src = x0 + (size_t)bid * TLEN;
        dst = out + (size_t)bid * TLEN;
        kblk = ch >> 8;
    } else {
        const int r = bid - BATCH * CH0;
        b = r / CH1;
        ch = r % CH1;
        src = x1 + (size_t)r * TLEN;
        dst = out + (size_t)BATCH * CH0 * TLEN + (size_t)r * TLEN;
        kblk = NB0 + (ch >> 8);
    }
    const int c = ch & (BC - 1);

    // Issue x loads before the dependency sync (independent of scores).
    const float4* s4 = reinterpret_cast<const float4*>(src);
    float4* d4 = reinterpret_cast<float4*>(dst);
    float4 v[4];
    #pragma unroll
    for (int i = 0; i < 4; ++i)
        v[i] = __ldcs(s4 + tid + i * 256);

    cudaGridDependencySynchronize();     // wait for g_scores

    __shared__ float a_s;
    if (tid == 0) {
        float sc[TB];
        float mx = -1e30f;
        #pragma unroll
        for (int k = 0; k < TB; ++k) {
            sc[k] = __ldg(&g_scores[(k * BATCH + b) * BC + c]);
            mx = fmaxf(mx, sc[k]);
        }
        float sum = 0.0f;
        #pragma unroll
        for (int k = 0; k < TB; ++k) sum += __expf(sc[k] - mx);
        a_s = __expf(sc[kblk] - mx) / sum;
    }
    __syncthreads();
    const float a = a_s;

    #pragma unroll
    for (int i = 0; i < 4; ++i) {
        v[i].x *= a; v[i].y *= a; v[i].z *= a; v[i].w *= a;
        __stcs(d4 + tid + i * 256, v[i]);
    }
}

// ---------------------------------------------------------------------------
extern "C" void kernel_launch(void* const* d_in, const int* in_sizes, int n_in,
                              void* d_out, int out_size) {
    const float* x0    = (const float*)d_in[0];  // [8,1024,4096]
    const float* x1    = (const float*)d_in[1];  // [8,768,4096]
    const float* W1    = (const float*)d_in[2];  // [256,64]
    const float* b1    = (const float*)d_in[3];  // [64]
    const float* gamma = (const float*)d_in[4];  // [64]
    const float* beta  = (const float*)d_in[5];  // [64]
    const float* Wh    = (const float*)d_in[6];  // [7,64,256]
    const float* bh    = (const float*)d_in[7];  // [7,256]
    float* out = (float*)d_out;

    // 1) gap (plain launch)
    gap_kernel<<<BATCH * BC, 256>>>(x0, x1);

    // 2) score — PDL on gap
    {
        cudaLaunchConfig_t cfg = {};
        cfg.gridDim = dim3(TB * BATCH);
        cfg.blockDim = dim3(256);
        cudaLaunchAttribute attr[1];
        attr[0].id = cudaLaunchAttributeProgrammaticStreamSerialization;
        attr[0].val.programmaticStreamSerializationAllowed = 1;
        cfg.attrs = attr;
        cfg.numAttrs = 1;
        cudaLaunchKernelEx(&cfg, score_kernel, W1, b1, gamma, beta, Wh, bh);
    }

    // 3) scale — PDL on score
    {
        cudaLaunchConfig_t cfg = {};
        cfg.gridDim = dim3(BATCH * (CH0 + CH1));
        cfg.blockDim = dim3(256);
        cudaLaunchAttribute attr[1];
        attr[0].id = cudaLaunchAttributeProgrammaticStreamSerialization;
        attr[0].val.programmaticStreamSerializationAllowed = 1;
        cfg.attrs = attr;
        cfg.numAttrs = 1;
        cudaLaunchKernelEx(&cfg, scale_kernel, x0, x1, out);
    }
}

// round 15
// speedup vs baseline: 1.0366x; 1.0366x over previous
#include <cuda_runtime.h>

// Problem constants (fixed shapes from reference)
#define BATCH 8
#define TLEN  4096
#define BC    256
#define RC    64
#define NB0   4
#define NB1   3
#define TB    7           // NB0 + NB1
#define CH0   1024        // x0 channels
#define CH1   768         // x1 channels

// L2 pinning with evict_last during the gap pass:
//   x0 rows with b < RES_B0 : 4*1024*16KB = 64 MB
//   x1 rows with b < RES_B1 : 2* 768*16KB = 24 MB   (total 88 MB < 126 MB L2)
// The scale pass re-reads these as L2 hits. Everything else streams evict-first.
#define RES_B0 4
#define RES_B1 2

// Device-global scratch (allocation-free per harness rules)
__device__ float g_gap[BATCH * BC];
__device__ float g_scores[TB * BATCH * BC];   // [k][b][c], raw scores

// 32-byte evict_last load (sm_103 ptxas requires v8.b32/v4.b64 for this hint)
__device__ __forceinline__ float ld_evict_last32_sum(const float* p) {
    unsigned long long r0, r1, r2, r3;
    asm volatile("ld.global.nc.L2::evict_last.v4.b64 {%0,%1,%2,%3}, [%4];"
                 : "=l"(r0), "=l"(r1), "=l"(r2), "=l"(r3) : "l"(p));
    float2 a = *reinterpret_cast<float2*>(&r0);
    float2 b = *reinterpret_cast<float2*>(&r1);
    float2 c = *reinterpret_cast<float2*>(&r2);
    float2 d = *reinterpret_cast<float2*>(&r3);
    return ((a.x + a.y) + (b.x + b.y)) + ((c.x + c.y) + (d.x + d.y));
}

// ---------------------------------------------------------------------------
// Kernel 1: block-sum over channel blocks + GAP over time.
// grid = 2048 blocks, 256 threads, min 8 CTAs/SM (keeps regs <= 32).
// Pinned rows use 32B evict_last loads; the rest stream evict-first.
// Triggers programmatic launch completion after publishing g_gap.
// ---------------------------------------------------------------------------
__global__ void __launch_bounds__(256, 8) gap_kernel(const float* __restrict__ x0,
                                                     const float* __restrict__ x1) {
    const int b = blockIdx.x >> 8;      // / BC
    const int c = blockIdx.x & (BC - 1);
    const int tid = threadIdx.x;

    float acc = 0.0f;

    if (b < RES_B0) {
        #pragma unroll
        for (int blk = 0; blk < NB0; ++blk) {
            const float* row = x0 + ((size_t)b * CH0 + (size_t)blk * BC + c) * TLEN;
            #pragma unroll
            for (int i = 0; i < 2; ++i)
                acc += ld_evict_last32_sum(row + (tid + i * 256) * 8);
        }
    } else {
        #pragma unroll
        for (int blk = 0; blk < NB0; ++blk) {
            const float4* row = reinterpret_cast<const float4*>(
                x0 + ((size_t)b * CH0 + (size_t)blk * BC + c) * TLEN);
            #pragma unroll
            for (int i = 0; i < 4; ++i) {
                float4 v = __ldcs(row + tid + i * 256);
                acc += (v.x + v.y) + (v.z + v.w);
            }
        }
    }
    if (b < RES_B1) {
        #pragma unroll
        for (int blk = 0; blk < NB1; ++blk) {
            const float* row = x1 + ((size_t)b * CH1 + (size_t)blk * BC + c) * TLEN;
            #pragma unroll
            for (int i = 0; i < 2; ++i)
                acc += ld_evict_last32_sum(row + (tid + i * 256) * 8);
        }
    } else {
        #pragma unroll
        for (int blk = 0; blk < NB1; ++blk) {
            const float4* row = reinterpret_cast<const float4*>(
                x1 + ((size_t)b * CH1 + (size_t)blk * BC + c) * TLEN);
            #pragma unroll
            for (int i = 0; i < 4; ++i) {
                float4 v = __ldcs(row + tid + i * 256);
                acc += (v.x + v.y) + (v.z + v.w);
            }
        }
    }

    // Block reduction
    __shared__ float warpsum[8];
    #pragma unroll
    for (int o = 16; o > 0; o >>= 1)
        acc += __shfl_down_sync(0xffffffffu, acc, o);
    if ((tid & 31) == 0) warpsum[tid >> 5] = acc;
    __syncthreads();
    if (tid < 8) {
        float v = warpsum[tid];
        #pragma unroll
        for (int o = 4; o > 0; o >>= 1)
            v += __shfl_down_sync(0x000000ffu, v, o);
        if (tid == 0) g_gap[b * BC + c] = v * (1.0f / (float)TLEN);
    }
    __syncthreads();
    cudaTriggerProgrammaticLaunchCompletion();
}

// ---------------------------------------------------------------------------
// Kernel 2: fused h + raw scores. grid = TB*BATCH (56) blocks x 256 threads.
// PDL-dependent on gap_kernel. The weights (W1/Wh/bh) do NOT depend on gap,
// so each CTA prefetches them to L2 BEFORE the dependency sync — the fetch
// overlaps gap's tail, and the post-sync FMA loops hit L2 instead of DRAM.
// ---------------------------------------------------------------------------
__global__ void __launch_bounds__(256) score_kernel(const float* __restrict__ W1,
                                                    const float* __restrict__ b1,
                                                    const float* __restrict__ gamma,
                                                    const float* __restrict__ beta,
                                                    const float* __restrict__ Wh,
                                                    const float* __restrict__ bh) {
    const int k = blockIdx.x >> 3;       // / BATCH
    const int b = blockIdx.x & 7;
    const int tid = threadIdx.x;

    __shared__ float part[4][RC];        // split-K partials
    __shared__ float h_s[RC];

    // --- pre-sync L2 prefetch of everything gap-independent ---
    {
        const char* whk = (const char*)(Wh + (size_t)k * RC * BC); // 64KB slice
        #pragma unroll
        for (int i = 0; i < 2; ++i)
            asm volatile("prefetch.global.L2 [%0];" :: "l"(whk + (tid + i * 256) * 128));
        const char* w1p = (const char*)W1;                          // 64KB
        #pragma unroll
        for (int i = 0; i < 2; ++i)
            asm volatile("prefetch.global.L2 [%0];" :: "l"(w1p + (tid + i * 256) * 128));
        if (tid < 8)
            asm volatile("prefetch.global.L2 [%0];" :: "l"((const char*)(bh + k * BC) + tid * 128));
    }

    cudaGridDependencySynchronize();     // wait for gap's g_gap writes

    // --- h[b] split-K: thread (s, r) accumulates over c in [s*64, s*64+64)
    {
        const int s = tid >> 6;          // 0..3
        const int r = tid & (RC - 1);    // 0..63
        const float* gp = &g_gap[b * BC + s * 64];
        const float* wp = W1 + (size_t)(s * 64) * RC + r;
        float acc = 0.0f;
        #pragma unroll 16
        for (int i = 0; i < 64; ++i)
            acc = fmaf(gp[i], wp[(size_t)i * RC], acc);   // coalesced: r varies
        part[s][r] = acc;
    }
    __syncthreads();
    if (tid < RC) {
        const int r = tid;
        float s = part[0][r] + part[1][r] + part[2][r] + part[3][r] + b1[r];
        const float bnscale = gamma[r] * rsqrtf(1.0f + 1e-5f);
        h_s[r] = fmaxf(fmaf(s, bnscale, beta[r]), 0.0f);
    }
    __syncthreads();

    // --- score[k][b][c], c = tid; Wh reads coalesced across c ---
    const int c = tid;
    float s = bh[k * BC + c];
    const float* w = Wh + (size_t)k * RC * BC + c;
    #pragma unroll 16
    for (int r = 0; r < RC; ++r)
        s = fmaf(h_s[r], w[(size_t)r * BC], s);
    g_scores[(k * BATCH + b) * BC + c] = s;

    cudaTriggerProgrammaticLaunchCompletion();
}

// ---------------------------------------------------------------------------
// Kernel 3: streaming scale with block-level fused softmax. PDL-dependent on
// score_kernel: each CTA issues its 4 independent x loads FIRST, then waits
// on the dependency, so the wait hides under the load latency.
// ---------------------------------------------------------------------------
__global__ void __launch_bounds__(256, 8) scale_kernel(const float* __restrict__ x0,
                                                       const float* __restrict__ x1,
                                                       float* __restrict__ out) {
    const int bid = blockIdx.x;
    const int tid = threadIdx.x;

    const float* src;
    float* dst;
    int b, ch, kblk;
    if (bid < BATCH * CH0) {
        b = bid >> 10;            // / CH0
        ch = bid & (CH0 - 1);
        src = x0 + (size_t)bid * TLEN;
        dst = out + (size_t)bid * TLEN;
        kblk = ch >> 8;
    } else {
        const int r = bid - BATCH * CH0;
        b = r / CH1;
        ch = r % CH1;
        src = x1 + (size_t)r * TLEN;
        dst = out + (size_t)BATCH * CH0 * TLEN + (size_t)r * TLEN;
        kblk = NB0 + (ch >> 8);
    }
    const int c = ch & (BC - 1);

    // Issue x loads before the dependency sync (independent of scores).
    const float4* s4 = reinterpret_cast<const float4*>(src);
    float4* d4 = reinterpret_cast<float4*>(dst);
    float4 v[4];
    #pragma unroll
    for (int i = 0; i < 4; ++i)
        v[i] = __ldcs(s4 + tid + i * 256);

    cudaGridDependencySynchronize();     // wait for g_scores

    __shared__ float a_s;
    if (tid == 0) {
        float sc[TB];
        float mx = -1e30f;
        #pragma unroll
        for (int k = 0; k < TB; ++k) {
            sc[k] = __ldg(&g_scores[(k * BATCH + b) * BC + c]);
            mx = fmaxf(mx, sc[k]);
        }
        float sum = 0.0f;
        #pragma unroll
        for (int k = 0; k < TB; ++k) sum += __expf(sc[k] - mx);
        a_s = __expf(sc[kblk] - mx) / sum;
    }
    __syncthreads();
    const float a = a_s;

    #pragma unroll
    for (int i = 0; i < 4; ++i) {
        v[i].x *= a; v[i].y *= a; v[i].z *= a; v[i].w *= a;
        __stcs(d4 + tid + i * 256, v[i]);
    }
}

// ---------------------------------------------------------------------------
extern "C" void kernel_launch(void* const* d_in, const int* in_sizes, int n_in,
                              void* d_out, int out_size) {
    const float* x0    = (const float*)d_in[0];  // [8,1024,4096]
    const float* x1    = (const float*)d_in[1];  // [8,768,4096]
    const float* W1    = (const float*)d_in[2];  // [256,64]
    const float* b1    = (const float*)d_in[3];  // [64]
    const float* gamma = (const float*)d_in[4];  // [64]
    const float* beta  = (const float*)d_in[5];  // [64]
    const float* Wh    = (const float*)d_in[6];  // [7,64,256]
    const float* bh    = (const float*)d_in[7];  // [7,256]
    float* out = (float*)d_out;

    // 1) gap (plain launch)
    gap_kernel<<<BATCH * BC, 256>>>(x0, x1);

    // 2) score — PDL on gap
    {
        cudaLaunchConfig_t cfg = {};
        cfg.gridDim = dim3(TB * BATCH);
        cfg.blockDim = dim3(256);
        cudaLaunchAttribute attr[1];
        attr[0].id = cudaLaunchAttributeProgrammaticStreamSerialization;
        attr[0].val.programmaticStreamSerializationAllowed = 1;
        cfg.attrs = attr;
        cfg.numAttrs = 1;
        cudaLaunchKernelEx(&cfg, score_kernel, W1, b1, gamma, beta, Wh, bh);
    }

    // 3) scale — PDL on score
    {
        cudaLaunchConfig_t cfg = {};
        cfg.gridDim = dim3(BATCH * (CH0 + CH1));
        cfg.blockDim = dim3(256);
        cudaLaunchAttribute attr[1];
        attr[0].id = cudaLaunchAttributeProgrammaticStreamSerialization;
        attr[0].val.programmaticStreamSerializationAllowed = 1;
        cfg.attrs = attr;
        cfg.numAttrs = 1;
        cudaLaunchKernelEx(&cfg, scale_kernel, x0, x1, out);
    }
}